// round 13
// baseline (speedup 1.0000x reference)
#include <cuda_runtime.h>

// Shapes fixed for this problem: B=64, C=2, H=W=512.
#define HW_SHIFT 18
#define HW (1 << HW_SHIFT)
#define KMAX 1000
#define NBUCK 1024                  // coarse buckets = top 10 bits of float pattern
#define CAP (1 << 21)               // candidate buffer per channel

// ---------------- device scratch (zero-init at load; reset per replay by
// k_prep / k_main last blocks, so graph replays are deterministic) ---------
__device__ double   g_pos_sum[2];
__device__ int      g_num_pos[2];
__device__ unsigned g_shist[2][NBUCK];
__device__ int      g_bcut[2];
__device__ int      g_cand_cnt[2];
__device__ float    g_cand[2][CAP];
__device__ unsigned g_done1;
__device__ unsigned g_done2;

// =============  K1: sampled histogram + bcut + accumulator reset  =========
// (identical to the R6/R7 fused kernel, which measured ~10us and worked)
__global__ void __launch_bounds__(1024) k_prep(
    const float* __restrict__ outp, const float* __restrict__ cm,
    const float* __restrict__ am, int N) {
  __shared__ unsigned hc[NBUCK], ha[NBUCK];
  __shared__ unsigned ss[NBUCK];
  __shared__ unsigned sh_last;
  __shared__ int sh_b;
  int tid = threadIdx.x;
  for (int i = tid; i < NBUCK; i += 1024) { hc[i] = 0u; ha[i] = 0u; }
  __syncthreads();
  int j = blockIdx.x * 1024 + tid;                 // sample index
  int i = ((j >> 5) << 11) + (j & 31);             // element index (coalesced chunks)
  if (i < N) {
    int b = i >> HW_SHIFT, s = i & (HW - 1);
    size_t base = ((size_t)b) << (HW_SHIFT + 1);
    float pc = outp[base + s], pa = outp[base + HW + s];
    if (cm[i] == 0.0f) { float v = pc * pc; atomicAdd(&hc[__float_as_uint(v) >> 22], 1u); }
    if (am[i] == 0.0f) { float v = pa * pa; atomicAdd(&ha[__float_as_uint(v) >> 22], 1u); }
  }
  __syncthreads();
  for (int q = tid; q < NBUCK; q += 1024) {
    if (hc[q]) atomicAdd(&g_shist[0][q], hc[q]);
    if (ha[q]) atomicAdd(&g_shist[1][q], ha[q]);
  }
  __threadfence();
  __syncthreads();
  if (tid == 0) sh_last = atomicAdd(&g_done1, 1u);
  __syncthreads();
  if (sh_last != gridDim.x - 1) return;

  // ---- last block: pick bcut = largest bucket with >=64 sampled at/above
  // (=> ~4096 true candidates >> KMAX w.h.p.), then reset accumulators ----
  for (int ch = 0; ch < 2; ch++) {
    ss[tid] = __ldcg(&g_shist[ch][tid]);
    __syncthreads();
    for (int off = 1; off < 1024; off <<= 1) {     // suffix (from-top) scan
      unsigned v = (tid + off < 1024) ? ss[tid + off] : 0u;
      __syncthreads();
      ss[tid] += v;
      __syncthreads();
    }
    if (tid == 0) sh_b = 0;
    __syncthreads();
    unsigned here = ss[tid];
    unsigned nxt = (tid < 1023) ? ss[tid + 1] : 0u;
    if (here >= 64u && nxt < 64u) sh_b = tid;      // unique (monotone suffix)
    __syncthreads();
    if (tid == 0) g_bcut[ch] = sh_b;
    g_shist[ch][tid] = 0u;                         // reset for next replay
    __syncthreads();
  }
  if (tid < 2) { g_pos_sum[tid] = 0.0; g_num_pos[tid] = 0; g_cand_cnt[tid] = 0; }
  if (tid == 0) g_done1 = 0u;
}

// ------------- exact boundary finder over a shared histogram -------------
// 256-thread version. cnt/fsum[M] built. Finds bucket t with
// sum(cnt[b>t]) < need <= +cnt[t]; adds sum(fsum[b>t]) into *sh_acc.
template <int M>
__device__ __forceinline__ void find_boundary(unsigned* cnt, float* fsum, unsigned* ss,
                                              int need, int tid,
                                              int* sh_t, int* sh_rem, double* sh_acc) {
  constexpr int CH = M / 256;
  unsigned csum = 0;
#pragma unroll
  for (int q = 0; q < CH; q++) csum += cnt[tid * CH + q];
  ss[tid] = csum;
  __syncthreads();
  for (int off = 1; off < 256; off <<= 1) {
    unsigned v = (tid + off < 256) ? ss[tid + off] : 0u;
    __syncthreads();
    ss[tid] += v;
    __syncthreads();
  }
  if (tid == 0) { *sh_t = -1; *sh_rem = 0; }
  __syncthreads();
  unsigned Tj = ss[tid];
  unsigned Tj1 = (tid < 255) ? ss[tid + 1] : 0u;
  if ((int)Tj1 < need && need <= (int)Tj) {        // exactly one thread
    int r = need - (int)Tj1;
#pragma unroll
    for (int q = CH - 1; q >= 0; q--) {
      unsigned c = cnt[tid * CH + q];
      if ((int)c < r) r -= (int)c;
      else { *sh_t = tid * CH + q; *sh_rem = r; break; }
    }
  }
  __syncthreads();
  int t = *sh_t;
  double part = 0.0;
  for (int bb = tid; bb < M; bb += 256)
    if (bb > t) part += (double)fsum[bb];
  for (int o = 16; o; o >>= 1) part += __shfl_down_sync(0xffffffffu, part, o);
  if ((tid & 31) == 0 && part != 0.0) atomicAdd(sh_acc, part);
  __syncthreads();
}

// ======  K2: R12 mainloop (verbatim) + last-block exact select  ===========
__global__ void __launch_bounds__(256, 8) k_main(
    const float* __restrict__ outp, const float* __restrict__ cm,
    const float* __restrict__ am, const float* __restrict__ cw,
    const float* __restrict__ aw, float* __restrict__ dout, int N) {
  const unsigned bc0 = (unsigned)g_bcut[0];
  const unsigned bc1 = (unsigned)g_bcut[1];
  float psC = 0.f, psA = 0.f;
  int npC = 0, npA = 0;
  int stride = blockDim.x * gridDim.x;
  for (int i = blockIdx.x * blockDim.x + threadIdx.x; i < N; i += stride) {
    int b = i >> HW_SHIFT, s = i & (HW - 1);
    size_t base = ((size_t)b) << (HW_SHIFT + 1);
    // ---- 6 independent loads, no load depends on another ----
    float pc = outp[base + s];
    float pa = outp[base + HW + s];
    float tc = cm[i];
    float ta = am[i];
    float wc = cw[i];
    float wa = aw[i];
    // ---- process (branches consume; no loads inside) ----
    if (tc != 0.0f) { float l = pc - tc; l *= l; psC += l * wc; npC++; }
    else {
      float v = pc * pc;
      if ((__float_as_uint(v) >> 22) >= bc0) {
        int idx = atomicAdd(&g_cand_cnt[0], 1);
        if (idx < CAP) g_cand[0][idx] = v;
      }
    }
    if (ta != 0.0f) { float l = pa - ta; l *= l; psA += l * wa; npA++; }
    else {
      float v = pa * pa;
      if ((__float_as_uint(v) >> 22) >= bc1) {
        int idx = atomicAdd(&g_cand_cnt[1], 1);
        if (idx < CAP) g_cand[1][idx] = v;
      }
    }
  }
  for (int o = 16; o; o >>= 1) {
    psC += __shfl_down_sync(0xffffffffu, psC, o);
    psA += __shfl_down_sync(0xffffffffu, psA, o);
    npC += __shfl_down_sync(0xffffffffu, npC, o);
    npA += __shfl_down_sync(0xffffffffu, npA, o);
  }
  if ((threadIdx.x & 31) == 0) {
    atomicAdd(&g_pos_sum[0], (double)psC);
    atomicAdd(&g_pos_sum[1], (double)psA);
    atomicAdd(&g_num_pos[0], npC);
    atomicAdd(&g_num_pos[1], npA);
  }

  // -------- last-block ticket --------
  __threadfence();
  __syncthreads();
  __shared__ unsigned sh_last;
  if (threadIdx.x == 0) sh_last = atomicAdd(&g_done2, 1u);
  __syncthreads();
  if (sh_last != gridDim.x - 1) return;

  // -------- epilogue (one block, once): exact top-k both channels --------
  __shared__ unsigned cnt[2048];
  __shared__ float fsum[2048];
  __shared__ unsigned ssb[256];
  __shared__ int sh_t, sh_rem;
  __shared__ double sh_acc;
  int tid = threadIdx.x;
  double loss_total = 0.0;

  for (int ch = 0; ch < 2; ch++) {
    int n = __ldcg(&g_cand_cnt[ch]); if (n > CAP) n = CAP;
    int np = __ldcg(&g_num_pos[ch]);
    long long nn = (long long)N - np;
    long long kk = 4LL * (long long)np;
    if (kk > KMAX) kk = KMAX;
    if (kk > nn) kk = nn;
    if (kk < 0) kk = 0;
    int k = (int)kk;
    if (tid == 0) sh_acc = 0.0;
    __syncthreads();

    int t0 = -1, t1 = -1;
    int need = k;
    if (need > 0) {                                 // level 0: bits [31:22]
      for (int i2 = tid; i2 < 1024; i2 += 256) { cnt[i2] = 0u; fsum[i2] = 0.f; }
      __syncthreads();
      for (int i2 = tid; i2 < n; i2 += 256) {
        float v = __ldcg(&g_cand[ch][i2]);
        unsigned b = __float_as_uint(v) >> 22;
        atomicAdd(&cnt[b], 1u); atomicAdd(&fsum[b], v);
      }
      __syncthreads();
      find_boundary<1024>(cnt, fsum, ssb, need, tid, &sh_t, &sh_rem, &sh_acc);
      t0 = sh_t; need = sh_rem;
    }
    if (need > 0 && t0 >= 0) {                      // level 1: bits [21:11]
      for (int i2 = tid; i2 < 2048; i2 += 256) { cnt[i2] = 0u; fsum[i2] = 0.f; }
      __syncthreads();
      for (int i2 = tid; i2 < n; i2 += 256) {
        float v = __ldcg(&g_cand[ch][i2]);
        unsigned u = __float_as_uint(v);
        if ((int)(u >> 22) == t0) {
          unsigned b = (u >> 11) & 2047u;
          atomicAdd(&cnt[b], 1u); atomicAdd(&fsum[b], v);
        }
      }
      __syncthreads();
      find_boundary<2048>(cnt, fsum, ssb, need, tid, &sh_t, &sh_rem, &sh_acc);
      t1 = sh_t; need = sh_rem;
    }
    if (need > 0 && t1 >= 0) {                      // level 2: bits [10:0]
      for (int i2 = tid; i2 < 2048; i2 += 256) { cnt[i2] = 0u; fsum[i2] = 0.f; }
      __syncthreads();
      for (int i2 = tid; i2 < n; i2 += 256) {
        float v = __ldcg(&g_cand[ch][i2]);
        unsigned u = __float_as_uint(v);
        if ((int)(u >> 22) == t0 && (int)((u >> 11) & 2047u) == t1) {
          unsigned b = u & 2047u;
          atomicAdd(&cnt[b], 1u); atomicAdd(&fsum[b], v);
        }
      }
      __syncthreads();
      find_boundary<2048>(cnt, fsum, ssb, need, tid, &sh_t, &sh_rem, &sh_acc);
      if (tid == 0 && sh_t >= 0 && sh_rem > 0) {
        // all 32 bits fixed -> identical values; take rem copies exactly
        float v = __uint_as_float(((unsigned)t0 << 22) | ((unsigned)t1 << 11) | (unsigned)sh_t);
        atomicAdd(&sh_acc, (double)sh_rem * (double)v);
      }
      __syncthreads();
    }

    if (tid == 0) {
      double total = __ldcg(&g_pos_sum[ch]) + sh_acc;
      long long denom = (long long)np + k;
      loss_total += (denom > 0) ? (total / (double)denom) : 0.0;
    }
    __syncthreads();
  }

  if (tid == 0) {
    dout[0] = (float)loss_total;                    // direct store: no init node
    g_done2 = 0u;                                   // reset for next replay
  }
}

// ---------------- launcher: 2 graph nodes ----------------
extern "C" void kernel_launch(void* const* d_in, const int* in_sizes, int n_in,
                              void* d_out, int out_size) {
  const float* outp = (const float*)d_in[0];
  const float* cm   = (const float*)d_in[1];
  const float* am   = (const float*)d_in[2];
  const float* cw   = (const float*)d_in[3];
  const float* aw   = (const float*)d_in[4];
  float* o = (float*)d_out;
  int N = in_sizes[1];                              // B*H*W = 16,777,216

  int nsamp = N / 64;
  k_prep<<<(nsamp + 1023) / 1024, 1024>>>(outp, cm, am, N);
  k_main<<<1184, 256>>>(outp, cm, am, cw, aw, o, N);  // 8 CTAs/SM * 148 SMs
}

// round 14
// speedup vs baseline: 1.0697x; 1.0697x over previous
#include <cuda_runtime.h>

// Shapes fixed for this problem: B=64, C=2, H=W=512.
#define HW_SHIFT 18
#define HW (1 << HW_SHIFT)
#define KMAX 1000
#define NBUCK 1024                  // coarse buckets = top 10 bits of float pattern
#define CAP (1 << 21)               // candidate buffer per channel

// ---------------- device scratch (zero-init at load; reset per replay by
// k_prep's last block, so graph replays are deterministic) -----------------
__device__ double   g_pos_sum[2];
__device__ int      g_num_pos[2];
__device__ unsigned g_shist[2][NBUCK];
__device__ int      g_bcut[2];
__device__ int      g_cand_cnt[2];
__device__ float    g_cand[2][CAP];
__device__ unsigned g_done1;

// =============  K1: sampled histogram + bcut + accumulator reset  =========
// (identical to R13's k_prep, which measured ~10us)
__global__ void __launch_bounds__(1024) k_prep(
    const float* __restrict__ outp, const float* __restrict__ cm,
    const float* __restrict__ am, int N) {
  __shared__ unsigned hc[NBUCK], ha[NBUCK];
  __shared__ unsigned ss[NBUCK];
  __shared__ unsigned sh_last;
  __shared__ int sh_b;
  int tid = threadIdx.x;
  for (int i = tid; i < NBUCK; i += 1024) { hc[i] = 0u; ha[i] = 0u; }
  __syncthreads();
  int j = blockIdx.x * 1024 + tid;                 // sample index
  int i = ((j >> 5) << 11) + (j & 31);             // element index (coalesced chunks)
  if (i < N) {
    int b = i >> HW_SHIFT, s = i & (HW - 1);
    size_t base = ((size_t)b) << (HW_SHIFT + 1);
    float pc = outp[base + s], pa = outp[base + HW + s];
    if (cm[i] == 0.0f) { float v = pc * pc; atomicAdd(&hc[__float_as_uint(v) >> 22], 1u); }
    if (am[i] == 0.0f) { float v = pa * pa; atomicAdd(&ha[__float_as_uint(v) >> 22], 1u); }
  }
  __syncthreads();
  for (int q = tid; q < NBUCK; q += 1024) {
    if (hc[q]) atomicAdd(&g_shist[0][q], hc[q]);
    if (ha[q]) atomicAdd(&g_shist[1][q], ha[q]);
  }
  __threadfence();
  __syncthreads();
  if (tid == 0) sh_last = atomicAdd(&g_done1, 1u);
  __syncthreads();
  if (sh_last != gridDim.x - 1) return;

  // ---- last block: pick bcut = largest bucket with >=64 sampled at/above
  // (=> ~4096 true candidates >> KMAX w.h.p.), then reset accumulators ----
  for (int ch = 0; ch < 2; ch++) {
    ss[tid] = __ldcg(&g_shist[ch][tid]);
    __syncthreads();
    for (int off = 1; off < 1024; off <<= 1) {     // suffix (from-top) scan
      unsigned v = (tid + off < 1024) ? ss[tid + off] : 0u;
      __syncthreads();
      ss[tid] += v;
      __syncthreads();
    }
    if (tid == 0) sh_b = 0;
    __syncthreads();
    unsigned here = ss[tid];
    unsigned nxt = (tid < 1023) ? ss[tid + 1] : 0u;
    if (here >= 64u && nxt < 64u) sh_b = tid;      // unique (monotone suffix)
    __syncthreads();
    if (tid == 0) g_bcut[ch] = sh_b;
    g_shist[ch][tid] = 0u;                         // reset for next replay
    __syncthreads();
  }
  if (tid < 2) { g_pos_sum[tid] = 0.0; g_num_pos[tid] = 0; g_cand_cnt[tid] = 0; }
  if (tid == 0) g_done1 = 0u;
}

// ============  K2: the full scan — R12 VERBATIM (96.9us measured)  ========
__global__ void __launch_bounds__(256, 8) k_main(
    const float* __restrict__ outp, const float* __restrict__ cm,
    const float* __restrict__ am, const float* __restrict__ cw,
    const float* __restrict__ aw, int N) {
  const unsigned bc0 = (unsigned)g_bcut[0];
  const unsigned bc1 = (unsigned)g_bcut[1];
  float psC = 0.f, psA = 0.f;
  int npC = 0, npA = 0;
  int stride = blockDim.x * gridDim.x;
  for (int i = blockIdx.x * blockDim.x + threadIdx.x; i < N; i += stride) {
    int b = i >> HW_SHIFT, s = i & (HW - 1);
    size_t base = ((size_t)b) << (HW_SHIFT + 1);
    // ---- 6 independent loads, no load depends on another ----
    float pc = outp[base + s];
    float pa = outp[base + HW + s];
    float tc = cm[i];
    float ta = am[i];
    float wc = cw[i];
    float wa = aw[i];
    // ---- process (branches consume; no loads inside) ----
    if (tc != 0.0f) { float l = pc - tc; l *= l; psC += l * wc; npC++; }
    else {
      float v = pc * pc;
      if ((__float_as_uint(v) >> 22) >= bc0) {
        int idx = atomicAdd(&g_cand_cnt[0], 1);
        if (idx < CAP) g_cand[0][idx] = v;
      }
    }
    if (ta != 0.0f) { float l = pa - ta; l *= l; psA += l * wa; npA++; }
    else {
      float v = pa * pa;
      if ((__float_as_uint(v) >> 22) >= bc1) {
        int idx = atomicAdd(&g_cand_cnt[1], 1);
        if (idx < CAP) g_cand[1][idx] = v;
      }
    }
  }
  for (int o = 16; o; o >>= 1) {
    psC += __shfl_down_sync(0xffffffffu, psC, o);
    psA += __shfl_down_sync(0xffffffffu, psA, o);
    npC += __shfl_down_sync(0xffffffffu, npC, o);
    npA += __shfl_down_sync(0xffffffffu, npA, o);
  }
  if ((threadIdx.x & 31) == 0) {
    atomicAdd(&g_pos_sum[0], (double)psC);
    atomicAdd(&g_pos_sum[1], (double)psA);
    atomicAdd(&g_num_pos[0], npC);
    atomicAdd(&g_num_pos[1], npA);
  }
}

// ------------- exact boundary finder over a shared histogram -------------
// 1024-thread version. cnt/fsum[M] built. Finds bucket t with
// sum(cnt[b>t]) < need <= +cnt[t]; adds sum(fsum[b>t]) into *sh_acc.
template <int M>
__device__ __forceinline__ void find_boundary(unsigned* cnt, float* fsum, unsigned* ss,
                                              int need, int tid,
                                              int* sh_t, int* sh_rem, double* sh_acc) {
  constexpr int CH = M / 1024;
  unsigned csum = 0;
#pragma unroll
  for (int q = 0; q < CH; q++) csum += cnt[tid * CH + q];
  ss[tid] = csum;
  __syncthreads();
  for (int off = 1; off < 1024; off <<= 1) {
    unsigned v = (tid + off < 1024) ? ss[tid + off] : 0u;
    __syncthreads();
    ss[tid] += v;
    __syncthreads();
  }
  if (tid == 0) { *sh_t = -1; *sh_rem = 0; }
  __syncthreads();
  unsigned Tj = ss[tid];
  unsigned Tj1 = (tid < 1023) ? ss[tid + 1] : 0u;
  if ((int)Tj1 < need && need <= (int)Tj) {        // exactly one thread
    int r = need - (int)Tj1;
#pragma unroll
    for (int q = CH - 1; q >= 0; q--) {
      unsigned c = cnt[tid * CH + q];
      if ((int)c < r) r -= (int)c;
      else { *sh_t = tid * CH + q; *sh_rem = r; break; }
    }
  }
  __syncthreads();
  int t = *sh_t;
  double part = 0.0;
  for (int bb = tid; bb < M; bb += 1024)
    if (bb > t) part += (double)fsum[bb];
  for (int o = 16; o; o >>= 1) part += __shfl_down_sync(0xffffffffu, part, o);
  if ((tid & 31) == 0 && part != 0.0) atomicAdd(sh_acc, part);
  __syncthreads();
}

// ====  K3: single-block exact top-k, BOTH channels, direct dout store  ====
__global__ void __launch_bounds__(1024) k_select(float* __restrict__ dout, int N) {
  __shared__ unsigned cnt[2048];
  __shared__ float fsum[2048];
  __shared__ unsigned ss[1024];
  __shared__ int sh_t, sh_rem;
  __shared__ double sh_acc;
  int tid = threadIdx.x;
  double loss_total = 0.0;

  for (int ch = 0; ch < 2; ch++) {
    int n = g_cand_cnt[ch]; if (n > CAP) n = CAP;
    int np = g_num_pos[ch];
    long long nn = (long long)N - np;
    long long kk = 4LL * (long long)np;
    if (kk > KMAX) kk = KMAX;
    if (kk > nn) kk = nn;
    if (kk < 0) kk = 0;
    int k = (int)kk;
    if (tid == 0) sh_acc = 0.0;
    __syncthreads();

    int t0 = -1, t1 = -1;
    int need = k;
    if (need > 0) {                                 // level 0: bits [31:22]
      for (int i = tid; i < 1024; i += 1024) { cnt[i] = 0u; fsum[i] = 0.f; }
      __syncthreads();
      for (int i = tid; i < n; i += 1024) {
        float v = g_cand[ch][i];
        unsigned b = __float_as_uint(v) >> 22;
        atomicAdd(&cnt[b], 1u); atomicAdd(&fsum[b], v);
      }
      __syncthreads();
      find_boundary<1024>(cnt, fsum, ss, need, tid, &sh_t, &sh_rem, &sh_acc);
      t0 = sh_t; need = sh_rem;
    }
    if (need > 0 && t0 >= 0) {                      // level 1: bits [21:11]
      for (int i = tid; i < 2048; i += 1024) { cnt[i] = 0u; fsum[i] = 0.f; }
      __syncthreads();
      for (int i = tid; i < n; i += 1024) {
        float v = g_cand[ch][i];
        unsigned u = __float_as_uint(v);
        if ((int)(u >> 22) == t0) {
          unsigned b = (u >> 11) & 2047u;
          atomicAdd(&cnt[b], 1u); atomicAdd(&fsum[b], v);
        }
      }
      __syncthreads();
      find_boundary<2048>(cnt, fsum, ss, need, tid, &sh_t, &sh_rem, &sh_acc);
      t1 = sh_t; need = sh_rem;
    }
    if (need > 0 && t1 >= 0) {                      // level 2: bits [10:0]
      for (int i = tid; i < 2048; i += 1024) { cnt[i] = 0u; fsum[i] = 0.f; }
      __syncthreads();
      for (int i = tid; i < n; i += 1024) {
        float v = g_cand[ch][i];
        unsigned u = __float_as_uint(v);
        if ((int)(u >> 22) == t0 && (int)((u >> 11) & 2047u) == t1) {
          unsigned b = u & 2047u;
          atomicAdd(&cnt[b], 1u); atomicAdd(&fsum[b], v);
        }
      }
      __syncthreads();
      find_boundary<2048>(cnt, fsum, ss, need, tid, &sh_t, &sh_rem, &sh_acc);
      if (tid == 0 && sh_t >= 0 && sh_rem > 0) {
        // all 32 bits fixed -> identical values; take rem copies exactly
        float v = __uint_as_float(((unsigned)t0 << 22) | ((unsigned)t1 << 11) | (unsigned)sh_t);
        atomicAdd(&sh_acc, (double)sh_rem * (double)v);
      }
      __syncthreads();
    }

    if (tid == 0) {
      double total = g_pos_sum[ch] + sh_acc;
      long long denom = (long long)np + k;
      loss_total += (denom > 0) ? (total / (double)denom) : 0.0;
    }
    __syncthreads();
  }

  if (tid == 0) dout[0] = (float)loss_total;       // direct store: no init node
}

// ---------------- launcher: 3 graph nodes ----------------
extern "C" void kernel_launch(void* const* d_in, const int* in_sizes, int n_in,
                              void* d_out, int out_size) {
  const float* outp = (const float*)d_in[0];
  const float* cm   = (const float*)d_in[1];
  const float* am   = (const float*)d_in[2];
  const float* cw   = (const float*)d_in[3];
  const float* aw   = (const float*)d_in[4];
  float* o = (float*)d_out;
  int N = in_sizes[1];                              // B*H*W = 16,777,216

  int nsamp = N / 64;
  k_prep<<<(nsamp + 1023) / 1024, 1024>>>(outp, cm, am, N);
  k_main<<<1184, 256>>>(outp, cm, am, cw, aw, N);   // 8 CTAs/SM * 148 SMs
  k_select<<<1, 1024>>>(o, N);
}

// round 15
// speedup vs baseline: 1.0717x; 1.0019x over previous
#include <cuda_runtime.h>

// Shapes are fixed for this problem: B=64, C=2, H=W=512.
#define HW_SHIFT 18                 // log2(512*512)
#define HW (1 << HW_SHIFT)
#define KMAX 1000
#define NBUCK 1024                  // coarse buckets = top 10 bits of float pattern (u>>22)
#define CAP (1 << 21)               // candidate buffer per channel (2M floats)

// ---------------- device scratch (zero-init at load; each consumer resets
// what it read, so every graph replay starts from a clean state) -----------
__device__ double   g_pos_sum[2];
__device__ int      g_num_pos[2];
__device__ unsigned g_shist[2][NBUCK];   // sampled histogram of neg losses
__device__ int      g_bcut[2];           // bucket cutoff for candidate collection
__device__ int      g_cand_cnt[2];
__device__ float    g_cand[2][CAP];

// ---------------- pass 0: sampled histogram (1/64 of elements, contiguous
// 32-element chunks every 2048 so sampled reads stay fully coalesced).
// g_shist is zero on entry: zero-init at load, re-zeroed by k_bcut. --------
__global__ void k_sample(const float* __restrict__ outp,
                         const float* __restrict__ cm,
                         const float* __restrict__ am, int N) {
  __shared__ unsigned hc[NBUCK], ha[NBUCK];
  for (int i = threadIdx.x; i < NBUCK; i += blockDim.x) { hc[i] = 0u; ha[i] = 0u; }
  __syncthreads();
  int j = blockIdx.x * blockDim.x + threadIdx.x;      // sample index
  int i = ((j >> 5) << 11) + (j & 31);                 // element index
  if (i < N) {
    int b = i >> HW_SHIFT, s = i & (HW - 1);
    size_t base = ((size_t)b) << (HW_SHIFT + 1);       // b*2*HW
    float pc = outp[base + s], pa = outp[base + HW + s];
    if (cm[i] == 0.0f) { float v = pc * pc; atomicAdd(&hc[__float_as_uint(v) >> 22], 1u); }
    if (am[i] == 0.0f) { float v = pa * pa; atomicAdd(&ha[__float_as_uint(v) >> 22], 1u); }
  }
  __syncthreads();
  for (int q = threadIdx.x; q < NBUCK; q += blockDim.x) {
    if (hc[q]) atomicAdd(&g_shist[0][q], hc[q]);
    if (ha[q]) atomicAdd(&g_shist[1][q], ha[q]);
  }
}

// ---------------- pass B: pick b_cut = largest bucket with >=64 sampled
// values at or above it (=> ~4096 true candidates >> KMAX w.h.p.), then
// re-zero g_shist so the next replay's k_sample starts clean. --------------
__global__ void k_bcut() {
  __shared__ unsigned ss[1024];
  __shared__ int sh_b;
  int ch = blockIdx.x, tid = threadIdx.x;
  ss[tid] = g_shist[ch][tid];
  __syncthreads();
  g_shist[ch][tid] = 0u;                               // consumed -> reset
  for (int off = 1; off < 1024; off <<= 1) {           // suffix (from-top) scan
    unsigned v = (tid + off < 1024) ? ss[tid + off] : 0u;
    __syncthreads();
    ss[tid] += v;
    __syncthreads();
  }
  if (tid == 0) sh_b = 0;                              // default: collect everything
  __syncthreads();
  unsigned here = ss[tid];
  unsigned nxt = (tid < 1023) ? ss[tid + 1] : 0u;
  if (here >= 64u && nxt < 64u) sh_b = tid;            // unique (suffix sums monotone)
  __syncthreads();
  if (tid == 0) g_bcut[ch] = sh_b;
}

// ---------------- pass A: the full scan — R12 VERBATIM (96.9us measured) --
__global__ void __launch_bounds__(256, 8) k_main(
    const float* __restrict__ outp, const float* __restrict__ cm,
    const float* __restrict__ am, const float* __restrict__ cw,
    const float* __restrict__ aw, int N) {
  const unsigned bc0 = (unsigned)g_bcut[0];
  const unsigned bc1 = (unsigned)g_bcut[1];
  float psC = 0.f, psA = 0.f;
  int npC = 0, npA = 0;
  int stride = blockDim.x * gridDim.x;
  for (int i = blockIdx.x * blockDim.x + threadIdx.x; i < N; i += stride) {
    int b = i >> HW_SHIFT, s = i & (HW - 1);
    size_t base = ((size_t)b) << (HW_SHIFT + 1);
    // ---- 6 independent loads, no load depends on another ----
    float pc = outp[base + s];
    float pa = outp[base + HW + s];
    float tc = cm[i];
    float ta = am[i];
    float wc = cw[i];
    float wa = aw[i];
    // ---- process (branches consume; no loads inside) ----
    if (tc != 0.0f) { float l = pc - tc; l *= l; psC += l * wc; npC++; }
    else {
      float v = pc * pc;
      if ((__float_as_uint(v) >> 22) >= bc0) {
        int idx = atomicAdd(&g_cand_cnt[0], 1);
        if (idx < CAP) g_cand[0][idx] = v;
      }
    }
    if (ta != 0.0f) { float l = pa - ta; l *= l; psA += l * wa; npA++; }
    else {
      float v = pa * pa;
      if ((__float_as_uint(v) >> 22) >= bc1) {
        int idx = atomicAdd(&g_cand_cnt[1], 1);
        if (idx < CAP) g_cand[1][idx] = v;
      }
    }
  }
  for (int o = 16; o; o >>= 1) {
    psC += __shfl_down_sync(0xffffffffu, psC, o);
    psA += __shfl_down_sync(0xffffffffu, psA, o);
    npC += __shfl_down_sync(0xffffffffu, npC, o);
    npA += __shfl_down_sync(0xffffffffu, npA, o);
  }
  if ((threadIdx.x & 31) == 0) {
    atomicAdd(&g_pos_sum[0], (double)psC);
    atomicAdd(&g_pos_sum[1], (double)psA);
    atomicAdd(&g_num_pos[0], npC);
    atomicAdd(&g_num_pos[1], npA);
  }
}

// ---------------- exact boundary finder over a shared histogram ----------
// cnt/fsum[M] already built. Finds bucket t with: sum(cnt[b>t]) < need <= +cnt[t].
// Adds sum(fsum[b>t]) into *sh_acc. Leaves (t, remaining-in-t) in sh_t/sh_rem.
template <int M>
__device__ __forceinline__ void find_boundary(unsigned* cnt, float* fsum, unsigned* ss,
                                              int need, int tid,
                                              int* sh_t, int* sh_rem, double* sh_acc) {
  constexpr int CH = M / 1024;
  unsigned csum = 0;
#pragma unroll
  for (int q = 0; q < CH; q++) csum += cnt[tid * CH + q];
  ss[tid] = csum;
  __syncthreads();
  for (int off = 1; off < 1024; off <<= 1) {
    unsigned v = (tid + off < 1024) ? ss[tid + off] : 0u;
    __syncthreads();
    ss[tid] += v;
    __syncthreads();
  }
  if (tid == 0) { *sh_t = -1; *sh_rem = 0; }
  __syncthreads();
  unsigned Tj = ss[tid];
  unsigned Tj1 = (tid < 1023) ? ss[tid + 1] : 0u;
  if ((int)Tj1 < need && need <= (int)Tj) {            // exactly one thread
    int r = need - (int)Tj1;
#pragma unroll
    for (int q = CH - 1; q >= 0; q--) {
      unsigned c = cnt[tid * CH + q];
      if ((int)c < r) r -= (int)c;
      else { *sh_t = tid * CH + q; *sh_rem = r; break; }
    }
  }
  __syncthreads();
  int t = *sh_t;
  double part = 0.0;
  for (int bb = tid; bb < M; bb += 1024)
    if (bb > t) part += (double)fsum[bb];
  for (int o = 16; o; o >>= 1) part += __shfl_down_sync(0xffffffffu, part, o);
  if ((tid & 31) == 0 && part != 0.0) atomicAdd(sh_acc, part);
  __syncthreads();
}

// ---------------- pass D: single-block exact top-k for BOTH channels.
// Plain store to dout (no atomic => no init), then resets accumulators
// so the next graph replay starts clean. -----------------------------------
__global__ void __launch_bounds__(1024) k_select(float* __restrict__ dout, int N) {
  __shared__ unsigned cnt[2048];
  __shared__ float fsum[2048];
  __shared__ unsigned ss[1024];
  __shared__ int sh_t, sh_rem;
  __shared__ double sh_acc;
  int tid = threadIdx.x;
  double loss_total = 0.0;

  for (int ch = 0; ch < 2; ch++) {
    int n = g_cand_cnt[ch]; if (n > CAP) n = CAP;
    int np = g_num_pos[ch];
    long long nn = (long long)N - np;
    long long kk = 4LL * (long long)np;
    if (kk > KMAX) kk = KMAX;
    if (kk > nn) kk = nn;
    if (kk < 0) kk = 0;
    int k = (int)kk;
    if (tid == 0) sh_acc = 0.0;
    __syncthreads();

    int t0 = -1, t1 = -1;
    int need = k;
    if (need > 0) {                                     // level 0: bits [31:22]
      for (int i = tid; i < 1024; i += 1024) { cnt[i] = 0u; fsum[i] = 0.f; }
      __syncthreads();
      for (int i = tid; i < n; i += 1024) {
        float v = g_cand[ch][i];
        unsigned b = __float_as_uint(v) >> 22;
        atomicAdd(&cnt[b], 1u); atomicAdd(&fsum[b], v);
      }
      __syncthreads();
      find_boundary<1024>(cnt, fsum, ss, need, tid, &sh_t, &sh_rem, &sh_acc);
      t0 = sh_t; need = sh_rem;
    }
    if (need > 0 && t0 >= 0) {                          // level 1: bits [21:11]
      for (int i = tid; i < 2048; i += 1024) { cnt[i] = 0u; fsum[i] = 0.f; }
      __syncthreads();
      for (int i = tid; i < n; i += 1024) {
        float v = g_cand[ch][i];
        unsigned u = __float_as_uint(v);
        if ((int)(u >> 22) == t0) {
          unsigned b = (u >> 11) & 2047u;
          atomicAdd(&cnt[b], 1u); atomicAdd(&fsum[b], v);
        }
      }
      __syncthreads();
      find_boundary<2048>(cnt, fsum, ss, need, tid, &sh_t, &sh_rem, &sh_acc);
      t1 = sh_t; need = sh_rem;
    }
    if (need > 0 && t1 >= 0) {                          // level 2: bits [10:0]
      for (int i = tid; i < 2048; i += 1024) { cnt[i] = 0u; fsum[i] = 0.f; }
      __syncthreads();
      for (int i = tid; i < n; i += 1024) {
        float v = g_cand[ch][i];
        unsigned u = __float_as_uint(v);
        if ((int)(u >> 22) == t0 && (int)((u >> 11) & 2047u) == t1) {
          unsigned b = u & 2047u;
          atomicAdd(&cnt[b], 1u); atomicAdd(&fsum[b], v);
        }
      }
      __syncthreads();
      find_boundary<2048>(cnt, fsum, ss, need, tid, &sh_t, &sh_rem, &sh_acc);
      if (tid == 0 && sh_t >= 0 && sh_rem > 0) {
        // all 32 bits fixed -> identical values; take rem copies exactly
        float v = __uint_as_float(((unsigned)t0 << 22) | ((unsigned)t1 << 11) | (unsigned)sh_t);
        atomicAdd(&sh_acc, (double)sh_rem * (double)v);
      }
      __syncthreads();
    }

    if (tid == 0) {
      double total = g_pos_sum[ch] + sh_acc;
      long long denom = (long long)np + k;
      loss_total += (denom > 0) ? (total / (double)denom) : 0.0;
    }
    __syncthreads();
  }

  if (tid == 0) dout[0] = (float)loss_total;           // plain store
  // consumed -> reset for the next graph replay
  if (tid < 2) { g_pos_sum[tid] = 0.0; g_num_pos[tid] = 0; g_cand_cnt[tid] = 0; }
}

// ---------------- launcher: 4 graph nodes, no tickets ----------------
extern "C" void kernel_launch(void* const* d_in, const int* in_sizes, int n_in,
                              void* d_out, int out_size) {
  const float* outp = (const float*)d_in[0];
  const float* cm   = (const float*)d_in[1];
  const float* am   = (const float*)d_in[2];
  const float* cw   = (const float*)d_in[3];
  const float* aw   = (const float*)d_in[4];
  float* o = (float*)d_out;
  int N = in_sizes[1];                                  // B*H*W = 16,777,216

  int nsamp = N / 64;
  k_sample<<<(nsamp + 1023) / 1024, 1024>>>(outp, cm, am, N);
  k_bcut<<<2, 1024>>>();
  k_main<<<1184, 256>>>(outp, cm, am, cw, aw, N);       // 8 CTAs/SM * 148 SMs
  k_select<<<1, 1024>>>(o, N);
}

// round 16
// speedup vs baseline: 1.1857x; 1.1064x over previous
#include <cuda_runtime.h>

// Shapes are fixed for this problem: B=64, C=2, H=W=512.
#define HW_SHIFT 18                 // log2(512*512)
#define HW (1 << HW_SHIFT)
#define KMAX 1000
#define NBUCK 1024                  // coarse buckets = top 10 bits of float pattern (u>>22)
#define CAP (1 << 19)               // candidate buffer per channel (512K floats, ~16x margin)

// ---------------- device scratch (no allocations allowed) ----------------
__device__ double   g_pos_sum[2];
__device__ int      g_num_pos[2];
__device__ unsigned g_shist[2][NBUCK];   // sampled histogram of neg losses
__device__ int      g_bcut[2];           // bucket cutoff for candidate collection
__device__ int      g_cand_cnt[2];
__device__ float    g_cand[2][CAP];

// ---------------- init: zero accumulators + output ----------------
__global__ void k_init(float* dout) {
  int tid = blockIdx.x * blockDim.x + threadIdx.x;
  if (tid == 0) dout[0] = 0.0f;
  if (tid < 2) { g_pos_sum[tid] = 0.0; g_num_pos[tid] = 0; g_cand_cnt[tid] = 0; g_bcut[tid] = 0; }
  unsigned* sh = &g_shist[0][0];
  for (int i = tid; i < 2 * NBUCK; i += blockDim.x * gridDim.x) sh[i] = 0u;
}

// ---------------- pass 0: sampled histogram (1/64 of elements, contiguous
// 32-element chunks every 2048 so sampled reads stay fully coalesced) ------
__global__ void k_sample(const float* __restrict__ outp,
                         const float* __restrict__ cm,
                         const float* __restrict__ am, int N) {
  __shared__ unsigned hc[NBUCK], ha[NBUCK];
  for (int i = threadIdx.x; i < NBUCK; i += blockDim.x) { hc[i] = 0u; ha[i] = 0u; }
  __syncthreads();
  int j = blockIdx.x * blockDim.x + threadIdx.x;      // sample index
  int i = ((j >> 5) << 11) + (j & 31);                 // element index
  if (i < N) {
    int b = i >> HW_SHIFT, s = i & (HW - 1);
    size_t base = ((size_t)b) << (HW_SHIFT + 1);       // b*2*HW
    float pc = outp[base + s], pa = outp[base + HW + s];
    if (cm[i] == 0.0f) { float v = pc * pc; atomicAdd(&hc[__float_as_uint(v) >> 22], 1u); }
    if (am[i] == 0.0f) { float v = pa * pa; atomicAdd(&ha[__float_as_uint(v) >> 22], 1u); }
  }
  __syncthreads();
  for (int q = threadIdx.x; q < NBUCK; q += blockDim.x) {
    if (hc[q]) atomicAdd(&g_shist[0][q], hc[q]);
    if (ha[q]) atomicAdd(&g_shist[1][q], ha[q]);
  }
}

// ---------------- pass B: pick b_cut = largest bucket with >=64 sampled
// values at or above it  (=> ~4-32K true candidates >> KMAX w.h.p.) -------
__global__ void k_bcut() {
  __shared__ unsigned ss[1024];
  __shared__ int sh_b;
  int ch = blockIdx.x, tid = threadIdx.x;
  ss[tid] = g_shist[ch][tid];
  __syncthreads();
  for (int off = 1; off < 1024; off <<= 1) {           // suffix (from-top) scan
    unsigned v = (tid + off < 1024) ? ss[tid + off] : 0u;
    __syncthreads();
    ss[tid] += v;
    __syncthreads();
  }
  if (tid == 0) sh_b = 0;                              // default: collect everything
  __syncthreads();
  unsigned here = ss[tid];
  unsigned nxt = (tid < 1023) ? ss[tid + 1] : 0u;
  if (here >= 64u && nxt < 64u) sh_b = tid;            // unique (suffix sums monotone)
  __syncthreads();
  if (tid == 0) g_bcut[ch] = sh_b;
}

// ---------------- pass A: the full scan — R12 VERBATIM (96.9us measured) --
__global__ void __launch_bounds__(256, 8) k_main(
    const float* __restrict__ outp, const float* __restrict__ cm,
    const float* __restrict__ am, const float* __restrict__ cw,
    const float* __restrict__ aw, int N) {
  const unsigned bc0 = (unsigned)g_bcut[0];
  const unsigned bc1 = (unsigned)g_bcut[1];
  float psC = 0.f, psA = 0.f;
  int npC = 0, npA = 0;
  int stride = blockDim.x * gridDim.x;
  for (int i = blockIdx.x * blockDim.x + threadIdx.x; i < N; i += stride) {
    int b = i >> HW_SHIFT, s = i & (HW - 1);
    size_t base = ((size_t)b) << (HW_SHIFT + 1);
    // ---- 6 independent loads, no load depends on another ----
    float pc = outp[base + s];
    float pa = outp[base + HW + s];
    float tc = cm[i];
    float ta = am[i];
    float wc = cw[i];
    float wa = aw[i];
    // ---- process (branches consume; no loads inside) ----
    if (tc != 0.0f) { float l = pc - tc; l *= l; psC += l * wc; npC++; }
    else {
      float v = pc * pc;
      if ((__float_as_uint(v) >> 22) >= bc0) {
        int idx = atomicAdd(&g_cand_cnt[0], 1);
        if (idx < CAP) g_cand[0][idx] = v;
      }
    }
    if (ta != 0.0f) { float l = pa - ta; l *= l; psA += l * wa; npA++; }
    else {
      float v = pa * pa;
      if ((__float_as_uint(v) >> 22) >= bc1) {
        int idx = atomicAdd(&g_cand_cnt[1], 1);
        if (idx < CAP) g_cand[1][idx] = v;
      }
    }
  }
  for (int o = 16; o; o >>= 1) {
    psC += __shfl_down_sync(0xffffffffu, psC, o);
    psA += __shfl_down_sync(0xffffffffu, psA, o);
    npC += __shfl_down_sync(0xffffffffu, npC, o);
    npA += __shfl_down_sync(0xffffffffu, npA, o);
  }
  if ((threadIdx.x & 31) == 0) {
    atomicAdd(&g_pos_sum[0], (double)psC);
    atomicAdd(&g_pos_sum[1], (double)psA);
    atomicAdd(&g_num_pos[0], npC);
    atomicAdd(&g_num_pos[1], npA);
  }
}

// ---------------- exact boundary finder over a shared histogram ----------
// cnt/fsum[M] already built. Finds bucket t with: sum(cnt[b>t]) < need <= +cnt[t].
// Adds sum(fsum[b>t]) into *sh_acc. Leaves (t, remaining-in-t) in sh_t/sh_rem.
template <int M>
__device__ __forceinline__ void find_boundary(unsigned* cnt, float* fsum, unsigned* ss,
                                              int need, int tid,
                                              int* sh_t, int* sh_rem, double* sh_acc) {
  constexpr int CH = M / 1024;
  unsigned csum = 0;
#pragma unroll
  for (int q = 0; q < CH; q++) csum += cnt[tid * CH + q];
  ss[tid] = csum;
  __syncthreads();
  for (int off = 1; off < 1024; off <<= 1) {
    unsigned v = (tid + off < 1024) ? ss[tid + off] : 0u;
    __syncthreads();
    ss[tid] += v;
    __syncthreads();
  }
  if (tid == 0) { *sh_t = -1; *sh_rem = 0; }
  __syncthreads();
  unsigned Tj = ss[tid];
  unsigned Tj1 = (tid < 1023) ? ss[tid + 1] : 0u;
  if ((int)Tj1 < need && need <= (int)Tj) {            // exactly one thread
    int r = need - (int)Tj1;
#pragma unroll
    for (int q = CH - 1; q >= 0; q--) {
      unsigned c = cnt[tid * CH + q];
      if ((int)c < r) r -= (int)c;
      else { *sh_t = tid * CH + q; *sh_rem = r; break; }
    }
  }
  __syncthreads();
  int t = *sh_t;
  double part = 0.0;
  for (int bb = tid; bb < M; bb += 1024)
    if (bb > t) part += (double)fsum[bb];
  for (int o = 16; o; o >>= 1) part += __shfl_down_sync(0xffffffffu, part, o);
  if ((tid & 31) == 0 && part != 0.0) atomicAdd(sh_acc, part);
  __syncthreads();
}

// ---------------- pass D: exact top-k among candidates + final loss.
// One block per channel (parallel); scans are float4-vectorized so even a
// pathologically large cand_cnt costs ~1/4 the LDG issues of the old code.
__global__ void __launch_bounds__(1024) k_select(float* dout, int N) {
  __shared__ unsigned cnt[2048];
  __shared__ float fsum[2048];
  __shared__ unsigned ss[1024];
  __shared__ int sh_t, sh_rem;
  __shared__ double sh_acc;
  int ch = blockIdx.x, tid = threadIdx.x;
  int n = g_cand_cnt[ch]; if (n > CAP) n = CAP;
  int np = g_num_pos[ch];
  long long nn = (long long)N - np;
  long long kk = 4LL * (long long)np;
  if (kk > KMAX) kk = KMAX;
  if (kk > nn) kk = nn;
  if (kk < 0) kk = 0;
  int k = (int)kk;
  if (tid == 0) sh_acc = 0.0;
  __syncthreads();

  const int n4 = (n + 3) >> 2;
  int t0 = -1, t1 = -1;
  int need = k;
  if (need > 0) {                                       // level 0: bits [31:22]
    for (int i = tid; i < 1024; i += 1024) { cnt[i] = 0u; fsum[i] = 0.f; }
    __syncthreads();
    for (int i4 = tid; i4 < n4; i4 += 1024) {
      float4 v4 = *(const float4*)&g_cand[ch][i4 << 2];
      float vv[4] = {v4.x, v4.y, v4.z, v4.w};
      int base = i4 << 2;
#pragma unroll
      for (int e = 0; e < 4; e++) if (base + e < n) {
        unsigned b = __float_as_uint(vv[e]) >> 22;
        atomicAdd(&cnt[b], 1u); atomicAdd(&fsum[b], vv[e]);
      }
    }
    __syncthreads();
    find_boundary<1024>(cnt, fsum, ss, need, tid, &sh_t, &sh_rem, &sh_acc);
    t0 = sh_t; need = sh_rem;
  }
  if (need > 0 && t0 >= 0) {                            // level 1: bits [21:11]
    for (int i = tid; i < 2048; i += 1024) { cnt[i] = 0u; fsum[i] = 0.f; }
    __syncthreads();
    for (int i4 = tid; i4 < n4; i4 += 1024) {
      float4 v4 = *(const float4*)&g_cand[ch][i4 << 2];
      float vv[4] = {v4.x, v4.y, v4.z, v4.w};
      int base = i4 << 2;
#pragma unroll
      for (int e = 0; e < 4; e++) if (base + e < n) {
        unsigned u = __float_as_uint(vv[e]);
        if ((int)(u >> 22) == t0) {
          unsigned b = (u >> 11) & 2047u;
          atomicAdd(&cnt[b], 1u); atomicAdd(&fsum[b], vv[e]);
        }
      }
    }
    __syncthreads();
    find_boundary<2048>(cnt, fsum, ss, need, tid, &sh_t, &sh_rem, &sh_acc);
    t1 = sh_t; need = sh_rem;
  }
  if (need > 0 && t1 >= 0) {                            // level 2: bits [10:0]
    for (int i = tid; i < 2048; i += 1024) { cnt[i] = 0u; fsum[i] = 0.f; }
    __syncthreads();
    for (int i4 = tid; i4 < n4; i4 += 1024) {
      float4 v4 = *(const float4*)&g_cand[ch][i4 << 2];
      float vv[4] = {v4.x, v4.y, v4.z, v4.w};
      int base = i4 << 2;
#pragma unroll
      for (int e = 0; e < 4; e++) if (base + e < n) {
        unsigned u = __float_as_uint(vv[e]);
        if ((int)(u >> 22) == t0 && (int)((u >> 11) & 2047u) == t1) {
          unsigned b = u & 2047u;
          atomicAdd(&cnt[b], 1u); atomicAdd(&fsum[b], vv[e]);
        }
      }
    }
    __syncthreads();
    find_boundary<2048>(cnt, fsum, ss, need, tid, &sh_t, &sh_rem, &sh_acc);
    int t2 = sh_t, rem2 = sh_rem;
    if (tid == 0 && t2 >= 0 && rem2 > 0) {
      // all 32 bits fixed -> identical values; take rem2 copies exactly
      float v = __uint_as_float(((unsigned)t0 << 22) | ((unsigned)t1 << 11) | (unsigned)t2);
      atomicAdd(&sh_acc, (double)rem2 * (double)v);
    }
    __syncthreads();
  }

  if (tid == 0) {
    double total = g_pos_sum[ch] + sh_acc;
    long long denom = (long long)np + k;
    float loss = (denom > 0) ? (float)(total / (double)denom) : 0.0f;
    atomicAdd(dout, loss);                              // loss_char + loss_aff
  }
}

// ---------------- launcher ----------------
extern "C" void kernel_launch(void* const* d_in, const int* in_sizes, int n_in,
                              void* d_out, int out_size) {
  const float* outp = (const float*)d_in[0];
  const float* cm   = (const float*)d_in[1];
  const float* am   = (const float*)d_in[2];
  const float* cw   = (const float*)d_in[3];
  const float* aw   = (const float*)d_in[4];
  float* o = (float*)d_out;
  int N = in_sizes[1];                                  // B*H*W = 16,777,216

  k_init<<<2, 1024>>>(o);
  int nsamp = N / 64;
  k_sample<<<(nsamp + 1023) / 1024, 1024>>>(outp, cm, am, N);
  k_bcut<<<2, 1024>>>();
  k_main<<<1184, 256>>>(outp, cm, am, cw, aw, N);       // 8 CTAs/SM * 148 SMs, 100% occ
  k_select<<<2, 1024>>>(o, N);
}

// round 17
// speedup vs baseline: 2.9948x; 2.5257x over previous
#include <cuda_runtime.h>

// Shapes are fixed for this problem: B=64, C=2, H=W=512.
#define HW_SHIFT 18                 // log2(512*512)
#define HW (1 << HW_SHIFT)
#define KMAX 1000
#define NBUCK 8192                  // fine buckets = top 13 bits of float pattern (u>>19)
#define BTHRESH 40u                 // sampled-suffix threshold (=> ~2.5-10K true candidates)
#define CAP (1 << 19)               // candidate buffer per channel (512K floats)
#define SEL_CACHE 11776             // 46KB smem candidate cache in k_select

// ---------------- device scratch (no allocations allowed) ----------------
__device__ double   g_pos_sum[2];
__device__ int      g_num_pos[2];
__device__ unsigned g_shist[2][NBUCK];   // sampled histogram of neg losses
__device__ int      g_bcut[2];           // bucket cutoff for candidate collection
__device__ int      g_cand_cnt[2];
__device__ float    g_cand[2][CAP];

// ---------------- init: zero accumulators + output ----------------
__global__ void k_init(float* dout) {
  int tid = blockIdx.x * blockDim.x + threadIdx.x;
  if (tid == 0) dout[0] = 0.0f;
  if (tid < 2) { g_pos_sum[tid] = 0.0; g_num_pos[tid] = 0; g_cand_cnt[tid] = 0; g_bcut[tid] = 0; }
  unsigned* sh = &g_shist[0][0];
  for (int i = tid; i < 2 * NBUCK; i += blockDim.x * gridDim.x) sh[i] = 0u;
}

// ---------------- pass 0: sampled histogram (1/64 of elements, contiguous
// 32-element chunks every 2048 -> coalesced). One channel per blockIdx.y so
// the 8192-bin histogram (32KB) fits static smem. u32 atomics only (native).
__global__ void k_sample(const float* __restrict__ outp,
                         const float* __restrict__ cm,
                         const float* __restrict__ am, int N) {
  __shared__ unsigned h[NBUCK];
  int tid = threadIdx.x;
  int ch = blockIdx.y;
  for (int i = tid; i < NBUCK; i += 1024) h[i] = 0u;
  __syncthreads();
  int j = blockIdx.x * 1024 + tid;                     // sample index
  int i = ((j >> 5) << 11) + (j & 31);                 // element index
  if (i < N) {
    int b = i >> HW_SHIFT, s = i & (HW - 1);
    size_t base = ((size_t)b) << (HW_SHIFT + 1);       // b*2*HW
    const float* map = ch ? am : cm;
    float p = outp[base + (ch ? HW : 0) + s];
    if (map[i] == 0.0f) {
      float v = p * p;
      atomicAdd(&h[__float_as_uint(v) >> 19], 1u);
    }
  }
  __syncthreads();
  for (int q = tid; q < NBUCK; q += 1024)
    if (h[q]) atomicAdd(&g_shist[ch][q], h[q]);
}

// ---------------- pass B: pick b_cut = largest bin with sampled-suffix
// >= BTHRESH  (=> true candidates in [~1.3K, ~10K], always >= k w.h.p.) ----
__global__ void k_bcut() {
  __shared__ unsigned ss[1024];
  __shared__ int sh_b;
  int ch = blockIdx.x, tid = threadIdx.x;
  unsigned loc[8];
  unsigned lsum = 0;
#pragma unroll
  for (int q = 0; q < 8; q++) { loc[q] = g_shist[ch][tid * 8 + q]; lsum += loc[q]; }
  ss[tid] = lsum;
  __syncthreads();
  for (int off = 1; off < 1024; off <<= 1) {           // suffix (from-top) scan
    unsigned v = (tid + off < 1024) ? ss[tid + off] : 0u;
    __syncthreads();
    ss[tid] += v;
    __syncthreads();
  }
  if (tid == 0) sh_b = 0;                              // default: collect everything
  __syncthreads();
  unsigned above = (tid < 1023) ? ss[tid + 1] : 0u;    // suffix above my 8-bin chunk
  unsigned mine = ss[tid];
  if (above < BTHRESH && BTHRESH <= mine) {            // exactly one thread
    unsigned run = above;
#pragma unroll
    for (int q = 7; q >= 0; q--) {
      run += loc[q];
      if (run >= BTHRESH) { sh_b = tid * 8 + q; break; }
    }
  }
  __syncthreads();
  if (tid == 0) g_bcut[ch] = sh_b;
}

// ---------------- pass A: the full scan — R12 body (96.9us measured); only
// the bucket shift changed (22 -> 19) to match the finer histogram. --------
__global__ void __launch_bounds__(256, 8) k_main(
    const float* __restrict__ outp, const float* __restrict__ cm,
    const float* __restrict__ am, const float* __restrict__ cw,
    const float* __restrict__ aw, int N) {
  const unsigned bc0 = (unsigned)g_bcut[0];
  const unsigned bc1 = (unsigned)g_bcut[1];
  float psC = 0.f, psA = 0.f;
  int npC = 0, npA = 0;
  int stride = blockDim.x * gridDim.x;
  for (int i = blockIdx.x * blockDim.x + threadIdx.x; i < N; i += stride) {
    int b = i >> HW_SHIFT, s = i & (HW - 1);
    size_t base = ((size_t)b) << (HW_SHIFT + 1);
    // ---- 6 independent loads, no load depends on another ----
    float pc = outp[base + s];
    float pa = outp[base + HW + s];
    float tc = cm[i];
    float ta = am[i];
    float wc = cw[i];
    float wa = aw[i];
    // ---- process (branches consume; no loads inside) ----
    if (tc != 0.0f) { float l = pc - tc; l *= l; psC += l * wc; npC++; }
    else {
      float v = pc * pc;
      if ((__float_as_uint(v) >> 19) >= bc0) {
        int idx = atomicAdd(&g_cand_cnt[0], 1);
        if (idx < CAP) g_cand[0][idx] = v;
      }
    }
    if (ta != 0.0f) { float l = pa - ta; l *= l; psA += l * wa; npA++; }
    else {
      float v = pa * pa;
      if ((__float_as_uint(v) >> 19) >= bc1) {
        int idx = atomicAdd(&g_cand_cnt[1], 1);
        if (idx < CAP) g_cand[1][idx] = v;
      }
    }
  }
  for (int o = 16; o; o >>= 1) {
    psC += __shfl_down_sync(0xffffffffu, psC, o);
    psA += __shfl_down_sync(0xffffffffu, psA, o);
    npC += __shfl_down_sync(0xffffffffu, npC, o);
    npA += __shfl_down_sync(0xffffffffu, npA, o);
  }
  if ((threadIdx.x & 31) == 0) {
    atomicAdd(&g_pos_sum[0], (double)psC);
    atomicAdd(&g_pos_sum[1], (double)psA);
    atomicAdd(&g_num_pos[0], npC);
    atomicAdd(&g_num_pos[1], npA);
  }
}

// ---------------- pass D: exact top-k via ATOMIC-FREE MSB-radix select.
// One block per channel. 32 counting passes (ballot-free compare+reduce)
// find the k-th largest bit pattern P exactly (nonneg floats: uint order ==
// float order); then sum all v with u > P plus (k - count) copies of P.
// No shared-memory atomics anywhere (the f32 ATOMS CAS-spin storm is gone).
__global__ void __launch_bounds__(1024) k_select(float* dout, int N) {
  __shared__ float cache[SEL_CACHE];
  __shared__ int ism[32];
  __shared__ double dsm[32];
  int ch = blockIdx.x, tid = threadIdx.x;
  int lane = tid & 31, wid = tid >> 5;

  int n = g_cand_cnt[ch]; if (n > CAP) n = CAP;
  int np = g_num_pos[ch];
  long long nn = (long long)N - np;
  long long kk = 4LL * (long long)np;
  if (kk > KMAX) kk = KMAX;
  if (kk > nn) kk = nn;
  if (kk < 0) kk = 0;
  int k = (int)kk;

  bool cached = (n <= SEL_CACHE);
  if (cached) {
    for (int i = tid; i < n; i += 1024) cache[i] = g_cand[ch][i];
  }
  __syncthreads();

  double acc = 0.0;
  if (k > 0) {
    unsigned prefix = 0;
    int rem = k;
    for (int bit = 31; bit >= 0; bit--) {
      unsigned pat = (prefix >> bit) | 1u;             // = (prefix | 1<<bit) >> bit
      int c = 0;
      for (int i = tid; i < n; i += 1024) {
        unsigned u = __float_as_uint(cached ? cache[i] : g_cand[ch][i]);
        c += ((u >> bit) == pat) ? 1 : 0;
      }
      for (int o = 16; o; o >>= 1) c += __shfl_down_sync(0xffffffffu, c, o);
      if (lane == 0) ism[wid] = c;
      __syncthreads();
      if (wid == 0) {
        int v = ism[lane];
        for (int o = 16; o; o >>= 1) v += __shfl_down_sync(0xffffffffu, v, o);
        if (lane == 0) ism[0] = v;
      }
      __syncthreads();
      c = ism[0];
      __syncthreads();                                  // ism reused next iter
      if (c >= rem) prefix |= (1u << bit);
      else rem -= c;
    }
    // prefix = k-th largest pattern; take all strictly-greater + rem ties
    double s = 0.0;
    for (int i = tid; i < n; i += 1024) {
      float v = cached ? cache[i] : g_cand[ch][i];
      if (__float_as_uint(v) > prefix) s += (double)v;
    }
    for (int o = 16; o; o >>= 1) s += __shfl_down_sync(0xffffffffu, s, o);
    if (lane == 0) dsm[wid] = s;
    __syncthreads();
    if (wid == 0) {
      double t = dsm[lane];
      for (int o = 16; o; o >>= 1) t += __shfl_down_sync(0xffffffffu, t, o);
      if (lane == 0) dsm[0] = t + (double)rem * (double)__uint_as_float(prefix);
    }
    __syncthreads();
    acc = dsm[0];
  }

  if (tid == 0) {
    double total = g_pos_sum[ch] + acc;
    long long denom = (long long)np + k;
    float loss = (denom > 0) ? (float)(total / (double)denom) : 0.0f;
    atomicAdd(dout, loss);                              // 2 global f32 atomics total
  }
}

// ---------------- launcher ----------------
extern "C" void kernel_launch(void* const* d_in, const int* in_sizes, int n_in,
                              void* d_out, int out_size) {
  const float* outp = (const float*)d_in[0];
  const float* cm   = (const float*)d_in[1];
  const float* am   = (const float*)d_in[2];
  const float* cw   = (const float*)d_in[3];
  const float* aw   = (const float*)d_in[4];
  float* o = (float*)d_out;
  int N = in_sizes[1];                                  // B*H*W = 16,777,216

  k_init<<<2, 1024>>>(o);
  int nsamp = N / 64;
  dim3 sgrid((nsamp + 1023) / 1024, 2);                 // x: samples, y: channel
  k_sample<<<sgrid, 1024>>>(outp, cm, am, N);
  k_bcut<<<2, 1024>>>();
  k_main<<<1184, 256>>>(outp, cm, am, cw, aw, N);       // 8 CTAs/SM * 148 SMs
  k_select<<<2, 1024>>>(o, N);
}